// round 3
// baseline (speedup 1.0000x reference)
#include <cuda_runtime.h>

#define RADIUS_F 5.0f
#define ECONV_F  14.399645f
#define MAX_ATOMS_COMB 262144
#define MOL_BITS 11
#define MOL_MASK 0x7FFu
#define REPS 32
#define MAX_BINS (2048 * REPS)

// Packed per-atom record: charge (f32, low 11 mantissa bits rounded to nearest)
// with mol index in those low 11 bits. One 4B gather gives qi+mol.
__device__ unsigned g_comb4[MAX_ATOMS_COMB];
// Replicated molecule bins: g_bins[rep * n_mol + mol], folded at the end.
__device__ float g_bins[MAX_BINS];

__global__ void prep_kernel(const float* __restrict__ charges,
                            const int*   __restrict__ mol_index,
                            int n_atoms, int n_bins, int pack)
{
    int i = blockIdx.x * blockDim.x + threadIdx.x;
    if (pack && i < n_atoms) {
        unsigned b = __float_as_uint(charges[i]);
        b += 0x400u;           // round-to-nearest on stolen bits
        b &= ~MOL_MASK;
        g_comb4[i] = b | (unsigned)mol_index[i];
    }
    if (i < n_bins) g_bins[i] = 0.0f;
}

__device__ __forceinline__ void accum_pair(
    float r, int fi, int si,
    const float* __restrict__ charges,
    float* __restrict__ mybins)   // = g_bins + lane * n_mol
{
    if (r < RADIUS_F) {
        unsigned b = g_comb4[fi];
        int   mol = (int)(b & MOL_MASK);
        float qi  = __uint_as_float(b & ~MOL_MASK);
        float qj  = __ldg(charges + si);
        float scr = 0.5f * (1.0f + cospif(r * (1.0f / RADIUS_F)));
        float e   = qi * qj * __fdividef(scr, r);
        atomicAdd(mybins + mol, e);   // no return use -> RED.E.ADD.F32 (L2-side)
    }
}

__global__ void __launch_bounds__(1024, 2)
pair_kernel(const float* __restrict__ pair_dist,
            const int*   __restrict__ pair_first,
            const int*   __restrict__ pair_second,
            const float* __restrict__ charges,
            int n_pairs, int n_mol)
{
    const int gtid   = blockIdx.x * blockDim.x + threadIdx.x;
    const int stride = gridDim.x * blockDim.x;
    const int n4     = n_pairs >> 2;
    const int lane   = threadIdx.x & 31;
    float* mybins    = g_bins + lane * n_mol;  // lanes of a warp never collide

    const float4* __restrict__ pd4 = (const float4*)pair_dist;
    const int4*   __restrict__ pf4 = (const int4*)pair_first;
    const int4*   __restrict__ ps4 = (const int4*)pair_second;

    for (int i = gtid; i < n4; i += stride) {
        float4 d = pd4[i];
        int4   f = pf4[i];
        int4   s = ps4[i];
        accum_pair(d.x, f.x, s.x, charges, mybins);
        accum_pair(d.y, f.y, s.y, charges, mybins);
        accum_pair(d.z, f.z, s.z, charges, mybins);
        accum_pair(d.w, f.w, s.w, charges, mybins);
    }
    for (int t = (n4 << 2) + gtid; t < n_pairs; t += stride) {
        accum_pair(pair_dist[t], pair_first[t], pair_second[t],
                   charges, mybins);
    }
}

__global__ void finish_kernel(float* __restrict__ out, int n_mol)
{
    int m = blockIdx.x * blockDim.x + threadIdx.x;
    if (m < n_mol) {
        float s = 0.0f;
        #pragma unroll
        for (int r = 0; r < REPS; r++)
            s += g_bins[r * n_mol + m];
        out[m] = 0.5f * ECONV_F * s;
    }
}

// ---- fallback path (shapes outside the fast-path assumptions) ----
__global__ void zero_out_kernel(float* __restrict__ out, int n)
{
    int i = blockIdx.x * blockDim.x + threadIdx.x;
    if (i < n) out[i] = 0.0f;
}

__global__ void pair_kernel_global(const float* __restrict__ pair_dist,
                                   const int*   __restrict__ pair_first,
                                   const int*   __restrict__ pair_second,
                                   const float* __restrict__ charges,
                                   const int*   __restrict__ mol_index,
                                   float* __restrict__ out, int n_pairs)
{
    const int gtid   = blockIdx.x * blockDim.x + threadIdx.x;
    const int stride = gridDim.x * blockDim.x;
    for (int i = gtid; i < n_pairs; i += stride) {
        float r = pair_dist[i];
        if (r < RADIUS_F) {
            int   fi  = pair_first[i];
            float qi  = __ldg(charges + fi);
            int   mol = __ldg(mol_index + fi);
            float qj  = __ldg(charges + pair_second[i]);
            float scr = 0.5f * (1.0f + cospif(r * (1.0f / RADIUS_F)));
            float e   = 0.5f * ECONV_F * qi * qj * __fdividef(scr, r);
            atomicAdd(out + mol, e);
        }
    }
}

extern "C" void kernel_launch(void* const* d_in, const int* in_sizes, int n_in,
                              void* d_out, int out_size)
{
    const float* charges     = (const float*)d_in[0];
    const float* pair_dist   = (const float*)d_in[1];
    const int*   pair_first  = (const int*)d_in[2];
    const int*   pair_second = (const int*)d_in[3];
    const int*   mol_index   = (const int*)d_in[4];

    int n_atoms = in_sizes[0];
    int n_pairs = in_sizes[1];
    int n_mol   = out_size;
    float* out  = (float*)d_out;

    bool fast = (n_atoms <= MAX_ATOMS_COMB) &&
                (n_mol <= (1 << MOL_BITS)) &&
                (n_mol * REPS <= MAX_BINS);

    if (fast) {
        int n_bins = n_mol * REPS;
        int prep_n = n_atoms > n_bins ? n_atoms : n_bins;
        prep_kernel<<<(prep_n + 255) / 256, 256>>>(charges, mol_index,
                                                   n_atoms, n_bins, 1);
        pair_kernel<<<296, 1024>>>(pair_dist, pair_first, pair_second,
                                   charges, n_pairs, n_mol);
        finish_kernel<<<(n_mol + 255) / 256, 256>>>(out, n_mol);
    } else {
        zero_out_kernel<<<(n_mol + 255) / 256, 256>>>(out, n_mol);
        pair_kernel_global<<<296, 1024>>>(pair_dist, pair_first, pair_second,
                                          charges, mol_index, out, n_pairs);
    }
}